// round 2
// baseline (speedup 1.0000x reference)
#include <cuda_runtime.h>

#define BB 2
#define NN 4096
#define CC 512
#define HH 8
#define DD 64
#define KP 512            // num pivots
#define BH (BB*HH)

// ---------------- scratch (static device arrays; no allocation allowed) ----
__device__ float  g_q[BB*HH*NN*DD];
__device__ float  g_k[BB*HH*NN*DD];
__device__ float  g_v[BB*HH*NN*DD];
__device__ float  g_L[BB*HH*NN];        // log2 of softmax denominator
__device__ float  g_o[BB*HH*NN*DD];     // attention output (pre-proj), [b,h,n,d]
__device__ float  g_out[BB*NN*CC];      // post-projection [b,n,c]
__device__ double g_imp[BB*NN];         // importance accumulators (fp64!)

// ---------------------------------------------------------------- utilities
__global__ void zero_imp_kernel() {
    int i = blockIdx.x * blockDim.x + threadIdx.x;
    if (i < BB*NN) g_imp[i] = 0.0;
}

// ------------------------------------------------- QKV GEMM: [8192,512]x[512,1536]
// 64x64 tile, BK=32, 256 threads, 4x4 microtile. Writes q/k/v in [b,h,n,d].
__global__ __launch_bounds__(256) void qkv_gemm_kernel(
        const float* __restrict__ x, const float* __restrict__ w) {
    __shared__ float As[64][36];   // [m][k], padded
    __shared__ float Bs[32][64];   // [k][n]
    int tid = threadIdx.x;
    int tx = tid & 15, ty = tid >> 4;
    int tx4 = tx * 4, ty4 = ty * 4;
    int m0 = blockIdx.y * 64;
    int j0 = blockIdx.x * 64;
    float acc[4][4] = {};
    for (int k0 = 0; k0 < 512; k0 += 32) {
        #pragma unroll
        for (int t = 0; t < 2; t++) {
            int l = tid + t * 256;             // 512 float4s of A tile (64x32)
            int r = l >> 3, c = (l & 7) * 4;
            *(float4*)&As[r][c] = *(const float4*)(x + (size_t)(m0 + r) * 512 + k0 + c);
        }
        #pragma unroll
        for (int t = 0; t < 2; t++) {
            int l = tid + t * 256;             // 512 float4s of B tile (32x64)
            int r = l >> 4, c = (l & 15) * 4;
            *(float4*)&Bs[r][c] = *(const float4*)(w + (size_t)(k0 + r) * 1536 + j0 + c);
        }
        __syncthreads();
        #pragma unroll 4
        for (int kk = 0; kk < 32; kk += 4) {
            float a[4][4], b[4][4];
            #pragma unroll
            for (int i = 0; i < 4; i++) *(float4*)a[i] = *(const float4*)&As[ty4 + i][kk];
            #pragma unroll
            for (int q = 0; q < 4; q++) *(float4*)b[q] = *(const float4*)&Bs[kk + q][tx4];
            #pragma unroll
            for (int q = 0; q < 4; q++)
                #pragma unroll
                for (int i = 0; i < 4; i++)
                    #pragma unroll
                    for (int j = 0; j < 4; j++)
                        acc[i][j] += a[i][q] * b[q][j];
        }
        __syncthreads();
    }
    // epilogue: column j0..j0+63 lies entirely in one (s,h) section
    int s = j0 >> 9;
    int h = (j0 >> 6) & 7;
    float* dst = (s == 0) ? g_q : ((s == 1) ? g_k : g_v);
    #pragma unroll
    for (int i = 0; i < 4; i++) {
        int m = m0 + ty4 + i;
        int b = m >> 12, n = m & 4095;
        float4 o4 = make_float4(acc[i][0], acc[i][1], acc[i][2], acc[i][3]);
        *(float4*)(dst + (size_t)((b * HH + h) * NN + n) * DD + tx4) = o4;
    }
}

// ------------------------------------------------- attention pass 1: L = log2 sum 2^s
// grid (N/64, B*H). Q pre-scaled by scale*log2e so we can use exp2.
__global__ __launch_bounds__(256) void attn_pass1_kernel() {
    __shared__ float Qs[64][68];   // [query][d]
    __shared__ float Ks[64][64];   // transposed+swizzled: Ks[d][key ^ (d&60)]
    int tid = threadIdx.x;
    int tx = tid & 15, ty = tid >> 4;
    int tx4 = tx * 4, ty4 = ty * 4;
    int bh = blockIdx.y;
    int n0 = blockIdx.x * 64;
    const float* Qg = g_q + (size_t)(bh * NN + n0) * DD;
    const float* Kg = g_k + (size_t)bh * NN * DD;
    const float sc = 0.125f * 1.4426950408889634f;   // scale * log2(e)
    #pragma unroll
    for (int t = 0; t < 4; t++) {
        int l = tid + t * 256;
        int r = l >> 4, c = (l & 15) * 4;
        float4 a = *(const float4*)(Qg + r * 64 + c);
        a.x *= sc; a.y *= sc; a.z *= sc; a.w *= sc;
        *(float4*)&Qs[r][c] = a;
    }
    float lacc[4] = {0.f, 0.f, 0.f, 0.f};
    for (int kt = 0; kt < 64; kt++) {
        __syncthreads();
        const float* Kt = Kg + (size_t)kt * 64 * DD;
        #pragma unroll
        for (int t = 0; t < 4; t++) {
            int l = tid + t * 256;
            int c = l >> 4, d0 = (l & 15) * 4;
            float4 a = *(const float4*)(Kt + c * 64 + d0);
            int cs = c ^ d0;                  // (d0+q)&60 == d0
            Ks[d0 + 0][cs] = a.x; Ks[d0 + 1][cs] = a.y;
            Ks[d0 + 2][cs] = a.z; Ks[d0 + 3][cs] = a.w;
        }
        __syncthreads();
        float s[4][4] = {};
        #pragma unroll 4
        for (int d4 = 0; d4 < 64; d4 += 4) {
            float qa[4][4], kb[4][4];
            #pragma unroll
            for (int i = 0; i < 4; i++) *(float4*)qa[i] = *(const float4*)&Qs[ty4 + i][d4];
            #pragma unroll
            for (int q = 0; q < 4; q++) *(float4*)kb[q] = *(const float4*)&Ks[d4 + q][tx4 ^ d4];
            #pragma unroll
            for (int q = 0; q < 4; q++)
                #pragma unroll
                for (int i = 0; i < 4; i++)
                    #pragma unroll
                    for (int j = 0; j < 4; j++)
                        s[i][j] += qa[i][q] * kb[q][j];
        }
        #pragma unroll
        for (int i = 0; i < 4; i++)
            #pragma unroll
            for (int j = 0; j < 4; j++)
                lacc[i] += exp2f(s[i][j]);
    }
    #pragma unroll
    for (int i = 0; i < 4; i++) {
        float v = lacc[i];
        v += __shfl_xor_sync(0xffffffffu, v, 8);
        v += __shfl_xor_sync(0xffffffffu, v, 4);
        v += __shfl_xor_sync(0xffffffffu, v, 2);
        v += __shfl_xor_sync(0xffffffffu, v, 1);
        if (tx == 0) g_L[(size_t)bh * NN + n0 + ty4 + i] = log2f(v);
    }
}

// ------------------------------------------------- attention pass 2: O = P@V, imp += colsum(P)
__global__ __launch_bounds__(256) void attn_pass2_kernel() {
    extern __shared__ float sm2[];
    float (*Qs)[68] = (float (*)[68])sm2;                                  // 64x68
    float (*Ks)[64] = (float (*)[64])(sm2 + 64 * 68);                      // 64x64 swz
    float (*Vs)[68] = (float (*)[68])(sm2 + 64 * 68 + 64 * 64);            // 64x68
    float (*Es)[68] = (float (*)[68])(sm2 + 64 * 68 * 2 + 64 * 64);       // 64x68
    int tid = threadIdx.x;
    int tx = tid & 15, ty = tid >> 4;
    int tx4 = tx * 4, ty4 = ty * 4;
    int bh = blockIdx.y;
    int b = bh >> 3;
    int n0 = blockIdx.x * 64;
    const float* Qg = g_q + (size_t)(bh * NN + n0) * DD;
    const float* Kg = g_k + (size_t)bh * NN * DD;
    const float* Vg = g_v + (size_t)bh * NN * DD;
    const float sc = 0.125f * 1.4426950408889634f;
    #pragma unroll
    for (int t = 0; t < 4; t++) {
        int l = tid + t * 256;
        int r = l >> 4, c = (l & 15) * 4;
        float4 a = *(const float4*)(Qg + r * 64 + c);
        a.x *= sc; a.y *= sc; a.z *= sc; a.w *= sc;
        *(float4*)&Qs[r][c] = a;
    }
    float Lr[4];
    #pragma unroll
    for (int i = 0; i < 4; i++) Lr[i] = g_L[(size_t)bh * NN + n0 + ty4 + i];
    float o[4][4] = {};
    for (int kt = 0; kt < 64; kt++) {
        __syncthreads();
        const float* Kt = Kg + (size_t)kt * 64 * DD;
        const float* Vt = Vg + (size_t)kt * 64 * DD;
        #pragma unroll
        for (int t = 0; t < 4; t++) {
            int l = tid + t * 256;
            int c = l >> 4, d0 = (l & 15) * 4;
            float4 a = *(const float4*)(Kt + c * 64 + d0);
            int cs = c ^ d0;
            Ks[d0 + 0][cs] = a.x; Ks[d0 + 1][cs] = a.y;
            Ks[d0 + 2][cs] = a.z; Ks[d0 + 3][cs] = a.w;
            *(float4*)&Vs[c][d0] = *(const float4*)(Vt + c * 64 + d0);
        }
        __syncthreads();
        float s[4][4] = {};
        #pragma unroll 4
        for (int d4 = 0; d4 < 64; d4 += 4) {
            float qa[4][4], kb[4][4];
            #pragma unroll
            for (int i = 0; i < 4; i++) *(float4*)qa[i] = *(const float4*)&Qs[ty4 + i][d4];
            #pragma unroll
            for (int q = 0; q < 4; q++) *(float4*)kb[q] = *(const float4*)&Ks[d4 + q][tx4 ^ d4];
            #pragma unroll
            for (int q = 0; q < 4; q++)
                #pragma unroll
                for (int i = 0; i < 4; i++)
                    #pragma unroll
                    for (int j = 0; j < 4; j++)
                        s[i][j] += qa[i][q] * kb[q][j];
        }
        #pragma unroll
        for (int i = 0; i < 4; i++) {
            float4 e4;
            e4.x = exp2f(s[i][0] - Lr[i]);
            e4.y = exp2f(s[i][1] - Lr[i]);
            e4.z = exp2f(s[i][2] - Lr[i]);
            e4.w = exp2f(s[i][3] - Lr[i]);
            *(float4*)&Es[ty4 + i][tx4] = e4;
        }
        __syncthreads();
        // P @ V
        #pragma unroll 4
        for (int c4 = 0; c4 < 64; c4 += 4) {
            float ea[4][4], vb[4][4];
            #pragma unroll
            for (int i = 0; i < 4; i++) *(float4*)ea[i] = *(const float4*)&Es[ty4 + i][c4];
            #pragma unroll
            for (int q = 0; q < 4; q++) *(float4*)vb[q] = *(const float4*)&Vs[c4 + q][tx4];
            #pragma unroll
            for (int q = 0; q < 4; q++)
                #pragma unroll
                for (int i = 0; i < 4; i++)
                    #pragma unroll
                    for (int j = 0; j < 4; j++)
                        o[i][j] += ea[i][q] * vb[q][j];
        }
        // per-key importance column sums — fp64 accumulation to make the
        // top-k ranking robust (boundary-rank flip caused the R0 failure)
        if (tid < 64) {
            double cs = 0.0;
            #pragma unroll 16
            for (int r = 0; r < 64; r++) cs += (double)Es[r][tid];
            atomicAdd(&g_imp[b * NN + kt * 64 + tid], cs);
        }
    }
    #pragma unroll
    for (int i = 0; i < 4; i++) {
        float4 o4 = make_float4(o[i][0], o[i][1], o[i][2], o[i][3]);
        *(float4*)(g_o + (size_t)(bh * NN + n0 + ty4 + i) * DD + tx4) = o4;
    }
}

// ------------------------------------------------- projection GEMM + bias
__global__ __launch_bounds__(256) void proj_gemm_kernel(
        const float* __restrict__ w, const float* __restrict__ bias) {
    __shared__ float As[64][36];
    __shared__ float Bs[32][64];
    int tid = threadIdx.x;
    int tx = tid & 15, ty = tid >> 4;
    int tx4 = tx * 4, ty4 = ty * 4;
    int m0 = blockIdx.y * 64;
    int j0 = blockIdx.x * 64;
    int bb = m0 >> 12, n0 = m0 & 4095;
    float acc[4][4] = {};
    for (int k0 = 0; k0 < 512; k0 += 32) {
        int h = k0 >> 6;
        int dd0 = k0 & 63;
        const float* Ap = g_o + (size_t)((bb * HH + h) * NN + n0) * DD + dd0;  // row stride 64
        #pragma unroll
        for (int t = 0; t < 2; t++) {
            int l = tid + t * 256;
            int r = l >> 3, c = (l & 7) * 4;
            *(float4*)&As[r][c] = *(const float4*)(Ap + (size_t)r * 64 + c);
        }
        #pragma unroll
        for (int t = 0; t < 2; t++) {
            int l = tid + t * 256;
            int r = l >> 4, c = (l & 15) * 4;
            *(float4*)&Bs[r][c] = *(const float4*)(w + (size_t)(k0 + r) * 512 + j0 + c);
        }
        __syncthreads();
        #pragma unroll 4
        for (int kk = 0; kk < 32; kk += 4) {
            float a[4][4], b[4][4];
            #pragma unroll
            for (int i = 0; i < 4; i++) *(float4*)a[i] = *(const float4*)&As[ty4 + i][kk];
            #pragma unroll
            for (int q = 0; q < 4; q++) *(float4*)b[q] = *(const float4*)&Bs[kk + q][tx4];
            #pragma unroll
            for (int q = 0; q < 4; q++)
                #pragma unroll
                for (int i = 0; i < 4; i++)
                    #pragma unroll
                    for (int j = 0; j < 4; j++)
                        acc[i][j] += a[i][q] * b[q][j];
        }
        __syncthreads();
    }
    float4 bi = *(const float4*)(bias + j0 + tx4);
    #pragma unroll
    for (int i = 0; i < 4; i++) {
        int m = m0 + ty4 + i;
        float4 o4 = make_float4(acc[i][0] + bi.x, acc[i][1] + bi.y,
                                acc[i][2] + bi.z, acc[i][3] + bi.w);
        *(float4*)(g_out + (size_t)m * CC + j0 + tx4) = o4;
    }
}

// ------------------------------------------------- top-K (bitonic sort on fp64) + gather
__global__ __launch_bounds__(1024) void topk_gather_kernel(float* __restrict__ out) {
    __shared__ double sv[4096];   // 32 KB
    __shared__ int    si[4096];   // 16 KB   (total 48 KB static)
    int b = blockIdx.x, tid = threadIdx.x;
    for (int t = tid; t < 4096; t += 1024) { sv[t] = g_imp[b * NN + t]; si[t] = t; }
    __syncthreads();
    for (int k = 2; k <= 4096; k <<= 1) {
        for (int j = k >> 1; j > 0; j >>= 1) {
            for (int t = tid; t < 4096; t += 1024) {
                int p = t ^ j;
                if (p > t) {
                    double va = sv[t], vb = sv[p];
                    int ia = si[t], ib = si[p];
                    // "before": descending value, ties -> ascending index (jax top_k order)
                    bool beforeAB = (va > vb) || (va == vb && ia < ib);
                    bool up = ((t & k) == 0);
                    if (up ? !beforeAB : beforeAB) {
                        sv[t] = vb; sv[p] = va; si[t] = ib; si[p] = ia;
                    }
                }
            }
            __syncthreads();
        }
    }
    for (int e = tid; e < KP * CC; e += 1024) {
        int kk = e >> 9, c = e & 511;
        out[(size_t)b * KP * CC + e] = g_out[(size_t)(b * NN + si[kk]) * CC + c];
    }
}

// ---------------------------------------------------------------- launcher
extern "C" void kernel_launch(void* const* d_in, const int* in_sizes, int n_in,
                              void* d_out, int out_size) {
    const float* x      = (const float*)d_in[0];
    const float* w_qkv  = (const float*)d_in[1];
    const float* w_proj = (const float*)d_in[2];
    const float* b_proj = (const float*)d_in[3];
    float* out = (float*)d_out;
    (void)in_sizes; (void)n_in; (void)out_size;

    const int smem2 = (64 * 68 * 3 + 64 * 64) * 4;   // 68608 B
    cudaFuncSetAttribute(attn_pass2_kernel,
                         cudaFuncAttributeMaxDynamicSharedMemorySize, smem2);

    zero_imp_kernel<<<8, 1024>>>();
    qkv_gemm_kernel<<<dim3(24, 128), 256>>>(x, w_qkv);
    attn_pass1_kernel<<<dim3(64, 16), 256>>>();
    attn_pass2_kernel<<<dim3(64, 16), 256, smem2>>>();
    proj_gemm_kernel<<<dim3(8, 128), 256>>>(w_proj, b_proj);
    topk_gather_kernel<<<2, 1024>>>(out);
}

// round 6
// speedup vs baseline: 1.8837x; 1.8837x over previous
#include <cuda_runtime.h>
#include <cuda_bf16.h>

#define BB 2
#define NN 4096
#define CC 512
#define HH 8
#define DD 64
#define KP 512
#define BH (BB*HH)

// ---------------- static device scratch (no allocation allowed) ------------
__device__ __nv_bfloat16 g_qh[BH*NN*DD];   // q*scale, bf16 hi
__device__ __nv_bfloat16 g_ql[BH*NN*DD];   // q*scale, bf16 lo
__device__ __nv_bfloat16 g_kh[BH*NN*DD];
__device__ __nv_bfloat16 g_kl[BH*NN*DD];
__device__ float         g_v [BH*NN*DD];
__device__ __nv_bfloat16 g_vth[BH*NN*DD];  // [bh][ktile(32)][d(64)][key(128)]
__device__ __nv_bfloat16 g_vtl[BH*NN*DD];
__device__ float         g_rinv[BH*NN];
__device__ float         g_o[BH*NN*DD];    // normalized attention out [b,h,n,d]
__device__ float         g_out[BB*NN*CC];
__device__ double        g_imp[BB*NN];

#define SC (0.125f * 1.4426950408889634f)  // headdim^-0.5 * log2(e)

// ---------------- helpers ---------------------------------------------------
__device__ __forceinline__ void mma16816(float* c, const unsigned* a,
                                         unsigned b0, unsigned b1) {
    asm volatile(
        "mma.sync.aligned.m16n8k16.row.col.f32.bf16.bf16.f32 "
        "{%0,%1,%2,%3}, {%4,%5,%6,%7}, {%8,%9}, {%0,%1,%2,%3};"
        : "+f"(c[0]), "+f"(c[1]), "+f"(c[2]), "+f"(c[3])
        : "r"(a[0]), "r"(a[1]), "r"(a[2]), "r"(a[3]), "r"(b0), "r"(b1));
}
__device__ __forceinline__ void split_store(__nv_bfloat16* hi, __nv_bfloat16* lo,
                                            size_t idx, float v) {
    __nv_bfloat16 h = __float2bfloat16(v);
    hi[idx] = h;
    lo[idx] = __float2bfloat16(v - __bfloat162float(h));
}
__device__ __forceinline__ unsigned pack2(float a, float b) {
    __nv_bfloat162 t = __floats2bfloat162_rn(a, b);
    return *(unsigned*)&t;
}
// split a float pair into bf16x2 hi + bf16x2 lo
__device__ __forceinline__ void split2(float a, float b, unsigned& hi, unsigned& lo) {
    float ha = __bfloat162float(__float2bfloat16(a));
    float hb = __bfloat162float(__float2bfloat16(b));
    hi = pack2(a, b);
    lo = pack2(a - ha, b - hb);
}

// ---------------------------------------------------------------- utilities
__global__ void zero_imp_kernel() {
    int i = blockIdx.x * blockDim.x + threadIdx.x;
    if (i < BB*NN) g_imp[i] = 0.0;
}

// ------------------------------------------------- QKV GEMM (scalar fp32)
__global__ __launch_bounds__(256) void qkv_gemm_kernel(
        const float* __restrict__ x, const float* __restrict__ w) {
    __shared__ float As[64][36];
    __shared__ float Bs[32][64];
    int tid = threadIdx.x;
    int tx = tid & 15, ty = tid >> 4;
    int tx4 = tx * 4, ty4 = ty * 4;
    int m0 = blockIdx.y * 64;
    int j0 = blockIdx.x * 64;
    float acc[4][4] = {};
    for (int k0 = 0; k0 < 512; k0 += 32) {
        #pragma unroll
        for (int t = 0; t < 2; t++) {
            int l = tid + t * 256;
            int r = l >> 3, c = (l & 7) * 4;
            *(float4*)&As[r][c] = *(const float4*)(x + (size_t)(m0 + r) * 512 + k0 + c);
        }
        #pragma unroll
        for (int t = 0; t < 2; t++) {
            int l = tid + t * 256;
            int r = l >> 4, c = (l & 15) * 4;
            *(float4*)&Bs[r][c] = *(const float4*)(w + (size_t)(k0 + r) * 1536 + j0 + c);
        }
        __syncthreads();
        #pragma unroll 4
        for (int kk = 0; kk < 32; kk += 4) {
            float a[4][4], b[4][4];
            #pragma unroll
            for (int i = 0; i < 4; i++) *(float4*)a[i] = *(const float4*)&As[ty4 + i][kk];
            #pragma unroll
            for (int q = 0; q < 4; q++) *(float4*)b[q] = *(const float4*)&Bs[kk + q][tx4];
            #pragma unroll
            for (int q = 0; q < 4; q++)
                #pragma unroll
                for (int i = 0; i < 4; i++)
                    #pragma unroll
                    for (int j = 0; j < 4; j++)
                        acc[i][j] += a[i][q] * b[q][j];
        }
        __syncthreads();
    }
    int s = j0 >> 9;
    int h = (j0 >> 6) & 7;
    #pragma unroll
    for (int i = 0; i < 4; i++) {
        int m = m0 + ty4 + i;
        int b = m >> 12, n = m & 4095;
        size_t base = ((size_t)(b * HH + h) * NN + n) * DD + tx4;
        if (s == 0) {
            #pragma unroll
            for (int j = 0; j < 4; j++) split_store(g_qh, g_ql, base + j, acc[i][j] * SC);
        } else if (s == 1) {
            #pragma unroll
            for (int j = 0; j < 4; j++) split_store(g_kh, g_kl, base + j, acc[i][j]);
        } else {
            *(float4*)(g_v + base) = make_float4(acc[i][0], acc[i][1], acc[i][2], acc[i][3]);
        }
    }
}

// ------------------------------------------------- V transpose + bf16 split
__global__ __launch_bounds__(256) void prep_v_kernel() {
    __shared__ float Vs[128][68];   // 272 B row stride: float4-aligned (R5 fix)
    int bh = blockIdx.y, kt = blockIdx.x, tid = threadIdx.x;
    const float* src = g_v + ((size_t)bh * NN + kt * 128) * DD;
    for (int i = tid; i < 2048; i += 256) {
        int r = i >> 4, c = (i & 15) * 4;
        *(float4*)&Vs[r][c] = *(const float4*)(src + r * 64 + c);
    }
    __syncthreads();
    __nv_bfloat16* dh = g_vth + (size_t)(bh * 32 + kt) * 64 * 128;
    __nv_bfloat16* dl = g_vtl + (size_t)(bh * 32 + kt) * 64 * 128;
    for (int j = tid; j < 8192; j += 256) {
        int d = j >> 7, k = j & 127;
        split_store(dh, dl, (size_t)d * 128 + k, Vs[k][d]);
    }
}

// ------------------------------------------------- attention pass 1 (mma.sync)
// per CTA: 128 queries x all keys; r = sum exp2(s). 8 warps, 16 q-rows each.
// smem: QH/QL/KH/KL each [128][72] bf16 (18432 B) -> 73728 B dynamic
#define A1_QH 0
#define A1_QL 18432
#define A1_KH 36864
#define A1_KL 55296
#define A1_SMEM 73728
__global__ __launch_bounds__(256) void attn1_mma_kernel() {
    extern __shared__ char sm[];
    __nv_bfloat16* QH = (__nv_bfloat16*)(sm + A1_QH);
    __nv_bfloat16* QL = (__nv_bfloat16*)(sm + A1_QL);
    __nv_bfloat16* KH = (__nv_bfloat16*)(sm + A1_KH);
    __nv_bfloat16* KL = (__nv_bfloat16*)(sm + A1_KL);
    int tid = threadIdx.x, wid = tid >> 5, lane = tid & 31;
    int bh = blockIdx.y, qt = blockIdx.x;

    {
        const __nv_bfloat16* qh = g_qh + ((size_t)bh * NN + qt * 128) * DD;
        const __nv_bfloat16* ql = g_ql + ((size_t)bh * NN + qt * 128) * DD;
        for (int i = tid; i < 1024; i += 256) {
            int r = i >> 3, j = i & 7;
            *(uint4*)(QH + r * 72 + j * 8) = *(const uint4*)(qh + r * 64 + j * 8);
            *(uint4*)(QL + r * 72 + j * 8) = *(const uint4*)(ql + r * 64 + j * 8);
        }
    }
    int qr = wid * 16;
    int arow = qr + (lane >> 2);
    float racc0 = 0.f, racc1 = 0.f;

    for (int kt = 0; kt < 32; kt++) {
        __syncthreads();
        {
            const __nv_bfloat16* kh = g_kh + ((size_t)bh * NN + kt * 128) * DD;
            const __nv_bfloat16* kl = g_kl + ((size_t)bh * NN + kt * 128) * DD;
            for (int i = tid; i < 1024; i += 256) {
                int r = i >> 3, j = i & 7;
                *(uint4*)(KH + r * 72 + j * 8) = *(const uint4*)(kh + r * 64 + j * 8);
                *(uint4*)(KL + r * 72 + j * 8) = *(const uint4*)(kl + r * 64 + j * 8);
            }
        }
        __syncthreads();
        float sacc[16][4] = {};
        #pragma unroll
        for (int kk = 0; kk < 4; kk++) {
            int acol = kk * 16 + (lane & 3) * 2;
            unsigned ah[4], al[4];
            ah[0] = *(unsigned*)(QH + arow * 72 + acol);
            ah[1] = *(unsigned*)(QH + (arow + 8) * 72 + acol);
            ah[2] = *(unsigned*)(QH + arow * 72 + acol + 8);
            ah[3] = *(unsigned*)(QH + (arow + 8) * 72 + acol + 8);
            al[0] = *(unsigned*)(QL + arow * 72 + acol);
            al[1] = *(unsigned*)(QL + (arow + 8) * 72 + acol);
            al[2] = *(unsigned*)(QL + arow * 72 + acol + 8);
            al[3] = *(unsigned*)(QL + (arow + 8) * 72 + acol + 8);
            #pragma unroll
            for (int nf = 0; nf < 16; nf++) {
                int brow = nf * 8 + (lane >> 2);
                unsigned b0 = *(unsigned*)(KH + brow * 72 + acol);
                unsigned b1 = *(unsigned*)(KH + brow * 72 + acol + 8);
                unsigned c0 = *(unsigned*)(KL + brow * 72 + acol);
                unsigned c1 = *(unsigned*)(KL + brow * 72 + acol + 8);
                mma16816(sacc[nf], ah, b0, b1);
                mma16816(sacc[nf], ah, c0, c1);
                mma16816(sacc[nf], al, b0, b1);
            }
        }
        #pragma unroll
        for (int nf = 0; nf < 16; nf++) {
            racc0 += exp2f(sacc[nf][0]) + exp2f(sacc[nf][1]);
            racc1 += exp2f(sacc[nf][2]) + exp2f(sacc[nf][3]);
        }
    }
    racc0 += __shfl_xor_sync(0xffffffffu, racc0, 1);
    racc0 += __shfl_xor_sync(0xffffffffu, racc0, 2);
    racc1 += __shfl_xor_sync(0xffffffffu, racc1, 1);
    racc1 += __shfl_xor_sync(0xffffffffu, racc1, 2);
    if ((lane & 3) == 0) {
        size_t base = (size_t)bh * NN + qt * 128 + qr + (lane >> 2);
        g_rinv[base]     = 1.0f / racc0;
        g_rinv[base + 8] = 1.0f / racc1;
    }
}

// ------------------------------------------------- attention pass 2 (mma.sync)
// recompute S; p = exp2(s)*rinv; importance colsums (fp32 smem -> fp64 global);
// O += P V via register-fragment P (no smem round-trip for P).
// smem: imp 512 B; QH/QL/KH/KL [128][72]; VH/VL [64][136] -> 109056 B dynamic
#define A2_IMP 0
#define A2_QH  512
#define A2_QL  (A2_QH + 18432)
#define A2_KH  (A2_QL + 18432)
#define A2_KL  (A2_KH + 18432)
#define A2_VH  (A2_KL + 18432)
#define A2_VL  (A2_VH + 17408)
#define A2_SMEM (A2_VL + 17408)
__global__ __launch_bounds__(256) void attn2_mma_kernel() {
    extern __shared__ char sm[];
    float* imp_s = (float*)(sm + A2_IMP);
    __nv_bfloat16* QH = (__nv_bfloat16*)(sm + A2_QH);
    __nv_bfloat16* QL = (__nv_bfloat16*)(sm + A2_QL);
    __nv_bfloat16* KH = (__nv_bfloat16*)(sm + A2_KH);
    __nv_bfloat16* KL = (__nv_bfloat16*)(sm + A2_KL);
    __nv_bfloat16* VH = (__nv_bfloat16*)(sm + A2_VH);
    __nv_bfloat16* VL = (__nv_bfloat16*)(sm + A2_VL);
    int tid = threadIdx.x, wid = tid >> 5, lane = tid & 31;
    int bh = blockIdx.y, qt = blockIdx.x;
    int b = bh >> 3;

    if (tid < 128) imp_s[tid] = 0.0f;
    {
        const __nv_bfloat16* qh = g_qh + ((size_t)bh * NN + qt * 128) * DD;
        const __nv_bfloat16* ql = g_ql + ((size_t)bh * NN + qt * 128) * DD;
        for (int i = tid; i < 1024; i += 256) {
            int r = i >> 3, j = i & 7;
            *(uint4*)(QH + r * 72 + j * 8) = *(const uint4*)(qh + r * 64 + j * 8);
            *(uint4*)(QL + r * 72 + j * 8) = *(const uint4*)(ql + r * 64 + j * 8);
        }
    }
    int qr = wid * 16;
    int arow = qr + (lane >> 2);
    float rinv0 = g_rinv[(size_t)bh * NN + qt * 128 + arow];
    float rinv1 = g_rinv[(size_t)bh * NN + qt * 128 + arow + 8];
    float oacc[8][4] = {};

    for (int kt = 0; kt < 32; kt++) {
        __syncthreads();
        {
            const __nv_bfloat16* kh = g_kh + ((size_t)bh * NN + kt * 128) * DD;
            const __nv_bfloat16* kl = g_kl + ((size_t)bh * NN + kt * 128) * DD;
            for (int i = tid; i < 1024; i += 256) {
                int r = i >> 3, j = i & 7;
                *(uint4*)(KH + r * 72 + j * 8) = *(const uint4*)(kh + r * 64 + j * 8);
                *(uint4*)(KL + r * 72 + j * 8) = *(const uint4*)(kl + r * 64 + j * 8);
            }
            const __nv_bfloat16* vh = g_vth + (size_t)(bh * 32 + kt) * 64 * 128;
            const __nv_bfloat16* vl = g_vtl + (size_t)(bh * 32 + kt) * 64 * 128;
            for (int i = tid; i < 1024; i += 256) {
                int r = i >> 4, j = i & 15;
                *(uint4*)(VH + r * 136 + j * 8) = *(const uint4*)(vh + r * 128 + j * 8);
                *(uint4*)(VL + r * 136 + j * 8) = *(const uint4*)(vl + r * 128 + j * 8);
            }
        }
        // warp 0 flushes previous tile's importance while others load (kt>0)
        if (wid == 0 && kt > 0) {
            #pragma unroll
            for (int j = 0; j < 4; j++) {
                int c = lane * 4 + j;
                atomicAdd(&g_imp[(size_t)b * NN + (kt - 1) * 128 + c], (double)imp_s[c]);
                imp_s[c] = 0.0f;
            }
        }
        __syncthreads();
        // ---- S = Q K^T (bf16 3-product split)
        float sacc[16][4] = {};
        #pragma unroll
        for (int kk = 0; kk < 4; kk++) {
            int acol = kk * 16 + (lane & 3) * 2;
            unsigned ah[4], al[4];
            ah[0] = *(unsigned*)(QH + arow * 72 + acol);
            ah[1] = *(unsigned*)(QH + (arow + 8) * 72 + acol);
            ah[2] = *(unsigned*)(QH + arow * 72 + acol + 8);
            ah[3] = *(unsigned*)(QH + (arow + 8) * 72 + acol + 8);
            al[0] = *(unsigned*)(QL + arow * 72 + acol);
            al[1] = *(unsigned*)(QL + (arow + 8) * 72 + acol);
            al[2] = *(unsigned*)(QL + arow * 72 + acol + 8);
            al[3] = *(unsigned*)(QL + (arow + 8) * 72 + acol + 8);
            #pragma unroll
            for (int nf = 0; nf < 16; nf++) {
                int brow = nf * 8 + (lane >> 2);
                unsigned b0 = *(unsigned*)(KH + brow * 72 + acol);
                unsigned b1 = *(unsigned*)(KH + brow * 72 + acol + 8);
                unsigned c0 = *(unsigned*)(KL + brow * 72 + acol);
                unsigned c1 = *(unsigned*)(KL + brow * 72 + acol + 8);
                mma16816(sacc[nf], ah, b0, b1);
                mma16816(sacc[nf], ah, c0, c1);
                mma16816(sacc[nf], al, b0, b1);
            }
        }
        // ---- p = exp2(s) * rinv; importance column sums
        #pragma unroll
        for (int nf = 0; nf < 16; nf++) {
            sacc[nf][0] = exp2f(sacc[nf][0]) * rinv0;
            sacc[nf][1] = exp2f(sacc[nf][1]) * rinv0;
            sacc[nf][2] = exp2f(sacc[nf][2]) * rinv1;
            sacc[nf][3] = exp2f(sacc[nf][3]) * rinv1;
            float s0 = sacc[nf][0] + sacc[nf][2];
            float s1 = sacc[nf][1] + sacc[nf][3];
            s0 += __shfl_xor_sync(0xffffffffu, s0, 4);
            s0 += __shfl_xor_sync(0xffffffffu, s0, 8);
            s0 += __shfl_xor_sync(0xffffffffu, s0, 16);
            s1 += __shfl_xor_sync(0xffffffffu, s1, 4);
            s1 += __shfl_xor_sync(0xffffffffu, s1, 8);
            s1 += __shfl_xor_sync(0xffffffffu, s1, 16);
            if (lane < 4) {
                atomicAdd(&imp_s[nf * 8 + lane * 2],     s0);
                atomicAdd(&imp_s[nf * 8 + lane * 2 + 1], s1);
            }
        }
        // ---- O += P V (P fragments built in registers from sacc)
        #pragma unroll
        for (int t = 0; t < 8; t++) {
            unsigned ah[4], al[4];
            split2(sacc[2*t][0],   sacc[2*t][1],   ah[0], al[0]);
            split2(sacc[2*t][2],   sacc[2*t][3],   ah[1], al[1]);
            split2(sacc[2*t+1][0], sacc[2*t+1][1], ah[2], al[2]);
            split2(sacc[2*t+1][2], sacc[2*t+1][3], ah[3], al[3]);
            int bcol = t * 16 + (lane & 3) * 2;
            #pragma unroll
            for (int nf = 0; nf < 8; nf++) {
                int brow = nf * 8 + (lane >> 2);
                unsigned b0 = *(unsigned*)(VH + brow * 136 + bcol);
                unsigned b1 = *(unsigned*)(VH + brow * 136 + bcol + 8);
                unsigned c0 = *(unsigned*)(VL + brow * 136 + bcol);
                unsigned c1 = *(unsigned*)(VL + brow * 136 + bcol + 8);
                mma16816(oacc[nf], ah, b0, b1);
                mma16816(oacc[nf], ah, c0, c1);
                mma16816(oacc[nf], al, b0, b1);
            }
        }
    }
    __syncthreads();
    if (wid == 0) {   // flush last tile's importance
        #pragma unroll
        for (int j = 0; j < 4; j++) {
            int c = lane * 4 + j;
            atomicAdd(&g_imp[(size_t)b * NN + 31 * 128 + c], (double)imp_s[c]);
        }
    }
    // ---- write O
    {
        size_t row0 = (size_t)bh * NN + qt * 128 + arow;
        float* o0 = g_o + row0 * DD;
        float* o1 = g_o + (row0 + 8) * DD;
        int col = (lane & 3) * 2;
        #pragma unroll
        for (int nf = 0; nf < 8; nf++) {
            *(float2*)(o0 + nf * 8 + col) = make_float2(oacc[nf][0], oacc[nf][1]);
            *(float2*)(o1 + nf * 8 + col) = make_float2(oacc[nf][2], oacc[nf][3]);
        }
    }
}

// ------------------------------------------------- projection GEMM + bias
__global__ __launch_bounds__(256) void proj_gemm_kernel(
        const float* __restrict__ w, const float* __restrict__ bias) {
    __shared__ float As[64][36];
    __shared__ float Bs[32][64];
    int tid = threadIdx.x;
    int tx = tid & 15, ty = tid >> 4;
    int tx4 = tx * 4, ty4 = ty * 4;
    int m0 = blockIdx.y * 64;
    int j0 = blockIdx.x * 64;
    int bb = m0 >> 12, n0 = m0 & 4095;
    float acc[4][4] = {};
    for (int k0 = 0; k0 < 512; k0 += 32) {
        int h = k0 >> 6;
        int dd0 = k0 & 63;
        const float* Ap = g_o + (size_t)((bb * HH + h) * NN + n0) * DD + dd0;
        #pragma unroll
        for (int t = 0; t < 2; t++) {
            int l = tid + t * 256;
            int r = l >> 3, c = (l & 7) * 4;
            *(float4*)&As[r][c] = *(const float4*)(Ap + (size_t)r * 64 + c);
        }
        #pragma unroll
        for (int t = 0; t < 2; t++) {
            int l = tid + t * 256;
            int r = l >> 4, c = (l & 15) * 4;
            *(float4*)&Bs[r][c] = *(const float4*)(w + (size_t)(k0 + r) * 512 + j0 + c);
        }
        __syncthreads();
        #pragma unroll 4
        for (int kk = 0; kk < 32; kk += 4) {
            float a[4][4], b[4][4];
            #pragma unroll
            for (int i = 0; i < 4; i++) *(float4*)a[i] = *(const float4*)&As[ty4 + i][kk];
            #pragma unroll
            for (int q = 0; q < 4; q++) *(float4*)b[q] = *(const float4*)&Bs[kk + q][tx4];
            #pragma unroll
            for (int q = 0; q < 4; q++)
                #pragma unroll
                for (int i = 0; i < 4; i++)
                    #pragma unroll
                    for (int j = 0; j < 4; j++)
                        acc[i][j] += a[i][q] * b[q][j];
        }
        __syncthreads();
    }
    float4 bi = *(const float4*)(bias + j0 + tx4);
    #pragma unroll
    for (int i = 0; i < 4; i++) {
        int m = m0 + ty4 + i;
        float4 o4 = make_float4(acc[i][0] + bi.x, acc[i][1] + bi.y,
                                acc[i][2] + bi.z, acc[i][3] + bi.w);
        *(float4*)(g_out + (size_t)m * CC + j0 + tx4) = o4;
    }
}

// ------------------------------------------------- top-K (bitonic, fp64) + gather
__global__ __launch_bounds__(1024) void topk_gather_kernel(float* __restrict__ out) {
    __shared__ double sv[4096];
    __shared__ int    si[4096];
    int b = blockIdx.x, tid = threadIdx.x;
    for (int t = tid; t < 4096; t += 1024) { sv[t] = g_imp[b * NN + t]; si[t] = t; }
    __syncthreads();
    for (int k = 2; k <= 4096; k <<= 1) {
        for (int j = k >> 1; j > 0; j >>= 1) {
            for (int t = tid; t < 4096; t += 1024) {
                int p = t ^ j;
                if (p > t) {
                    double va = sv[t], vb = sv[p];
                    int ia = si[t], ib = si[p];
                    bool beforeAB = (va > vb) || (va == vb && ia < ib);
                    bool up = ((t & k) == 0);
                    if (up ? !beforeAB : beforeAB) {
                        sv[t] = vb; sv[p] = va; si[t] = ib; si[p] = ia;
                    }
                }
            }
            __syncthreads();
        }
    }
    for (int e = tid; e < KP * CC; e += 1024) {
        int kk = e >> 9, c = e & 511;
        out[(size_t)b * KP * CC + e] = g_out[(size_t)(b * NN + si[kk]) * CC + c];
    }
}

// ---------------------------------------------------------------- launcher
extern "C" void kernel_launch(void* const* d_in, const int* in_sizes, int n_in,
                              void* d_out, int out_size) {
    const float* x      = (const float*)d_in[0];
    const float* w_qkv  = (const float*)d_in[1];
    const float* w_proj = (const float*)d_in[2];
    const float* b_proj = (const float*)d_in[3];
    float* out = (float*)d_out;
    (void)in_sizes; (void)n_in; (void)out_size;

    cudaFuncSetAttribute(attn1_mma_kernel,
                         cudaFuncAttributeMaxDynamicSharedMemorySize, A1_SMEM);
    cudaFuncSetAttribute(attn2_mma_kernel,
                         cudaFuncAttributeMaxDynamicSharedMemorySize, A2_SMEM);

    zero_imp_kernel<<<8, 1024>>>();
    qkv_gemm_kernel<<<dim3(24, 128), 256>>>(x, w_qkv);
    prep_v_kernel<<<dim3(32, 16), 256>>>();
    attn1_mma_kernel<<<dim3(32, 16), 256, A1_SMEM>>>();
    attn2_mma_kernel<<<dim3(32, 16), 256, A2_SMEM>>>();
    proj_gemm_kernel<<<dim3(8, 128), 256>>>(w_proj, b_proj);
    topk_gather_kernel<<<2, 1024>>>(out);
}

// round 11
// speedup vs baseline: 2.4041x; 1.2763x over previous
#include <cuda_runtime.h>
#include <cuda_bf16.h>

#define BB 2
#define NN 4096
#define CC 512
#define HH 8
#define DD 64
#define KP 512
#define BH (BB*HH)

// ---------------- static device scratch (no allocation allowed) ------------
__device__ __nv_bfloat16 g_qh[BH*NN*DD];   // q*scale, bf16 hi
__device__ __nv_bfloat16 g_ql[BH*NN*DD];   // q*scale, bf16 lo
__device__ __nv_bfloat16 g_kh[BH*NN*DD];
__device__ __nv_bfloat16 g_kl[BH*NN*DD];
__device__ float         g_v [BH*NN*DD];
__device__ __nv_bfloat16 g_vth[BH*NN*DD];  // [bh][kt][d][key]
__device__ __nv_bfloat16 g_vtl[BH*NN*DD];
__device__ float         g_rinv[BH*NN];
__device__ float         g_o[BH*NN*DD];    // attention out [b,h,n,d] fp32
__device__ float         g_out[BB*NN*CC];
__device__ double        g_imp[BB*NN];

#define SC (0.125f * 1.4426950408889634f)  // d^-0.5 * log2(e)

// ---------------- helpers ---------------------------------------------------
__device__ __forceinline__ void mma16816(float* c, const unsigned* a,
                                         unsigned b0, unsigned b1) {
    asm volatile(
        "mma.sync.aligned.m16n8k16.row.col.f32.bf16.bf16.f32 "
        "{%0,%1,%2,%3}, {%4,%5,%6,%7}, {%8,%9}, {%0,%1,%2,%3};"
        : "+f"(c[0]), "+f"(c[1]), "+f"(c[2]), "+f"(c[3])
        : "r"(a[0]), "r"(a[1]), "r"(a[2]), "r"(a[3]), "r"(b0), "r"(b1));
}
__device__ __forceinline__ unsigned smem_u32(const void* p) {
    unsigned a;
    asm("{ .reg .u64 t; cvta.to.shared.u64 t, %1; cvt.u32.u64 %0, t; }" : "=r"(a) : "l"(p));
    return a;
}
__device__ __forceinline__ void cp16(unsigned dst, const void* src) {
    asm volatile("cp.async.ca.shared.global [%0], [%1], 16;" :: "r"(dst), "l"(src));
}
#define CP_COMMIT() asm volatile("cp.async.commit_group;")
#define CP_WAIT(n)  asm volatile("cp.async.wait_group %0;" :: "n"(n))

__device__ __forceinline__ void split_store(__nv_bfloat16* hi, __nv_bfloat16* lo,
                                            size_t idx, float v) {
    __nv_bfloat16 h = __float2bfloat16(v);
    hi[idx] = h;
    lo[idx] = __float2bfloat16(v - __bfloat162float(h));
}
__device__ __forceinline__ unsigned pack2(float a, float b) {
    __nv_bfloat162 t = __floats2bfloat162_rn(a, b);
    return *(unsigned*)&t;
}
__device__ __forceinline__ void split2(float a, float b, unsigned& hi, unsigned& lo) {
    float ha = __bfloat162float(__float2bfloat16(a));
    float hb = __bfloat162float(__float2bfloat16(b));
    hi = pack2(a, b);
    lo = pack2(a - ha, b - hb);
}

// ---------------------------------------------------------------- utilities
__global__ void zero_imp_kernel() {
    int i = blockIdx.x * blockDim.x + threadIdx.x;
    if (i < BB*NN) g_imp[i] = 0.0;
}

// ------------------------------------------------- QKV GEMM (scalar, R6-proven)
__global__ __launch_bounds__(256) void qkv_gemm_kernel(
        const float* __restrict__ x, const float* __restrict__ w) {
    __shared__ float As[64][36];
    __shared__ float Bs[32][64];
    int tid = threadIdx.x;
    int tx = tid & 15, ty = tid >> 4;
    int tx4 = tx * 4, ty4 = ty * 4;
    int m0 = blockIdx.y * 64;
    int j0 = blockIdx.x * 64;
    float acc[4][4] = {};
    for (int k0 = 0; k0 < 512; k0 += 32) {
        #pragma unroll
        for (int t = 0; t < 2; t++) {
            int l = tid + t * 256;
            int r = l >> 3, c = (l & 7) * 4;
            *(float4*)&As[r][c] = *(const float4*)(x + (size_t)(m0 + r) * 512 + k0 + c);
        }
        #pragma unroll
        for (int t = 0; t < 2; t++) {
            int l = tid + t * 256;
            int r = l >> 4, c = (l & 15) * 4;
            *(float4*)&Bs[r][c] = *(const float4*)(w + (size_t)(k0 + r) * 1536 + j0 + c);
        }
        __syncthreads();
        #pragma unroll 4
        for (int kk = 0; kk < 32; kk += 4) {
            float a[4][4], b[4][4];
            #pragma unroll
            for (int i = 0; i < 4; i++) *(float4*)a[i] = *(const float4*)&As[ty4 + i][kk];
            #pragma unroll
            for (int q = 0; q < 4; q++) *(float4*)b[q] = *(const float4*)&Bs[kk + q][tx4];
            #pragma unroll
            for (int q = 0; q < 4; q++)
                #pragma unroll
                for (int i = 0; i < 4; i++)
                    #pragma unroll
                    for (int j = 0; j < 4; j++)
                        acc[i][j] += a[i][q] * b[q][j];
        }
        __syncthreads();
    }
    int s = j0 >> 9;
    int h = (j0 >> 6) & 7;
    #pragma unroll
    for (int i = 0; i < 4; i++) {
        int m = m0 + ty4 + i;
        int b = m >> 12, n = m & 4095;
        size_t base = ((size_t)(b * HH + h) * NN + n) * DD + tx4;
        if (s == 0) {
            #pragma unroll
            for (int j = 0; j < 4; j++) split_store(g_qh, g_ql, base + j, acc[i][j] * SC);
        } else if (s == 1) {
            #pragma unroll
            for (int j = 0; j < 4; j++) split_store(g_kh, g_kl, base + j, acc[i][j]);
        } else {
            *(float4*)(g_v + base) = make_float4(acc[i][0], acc[i][1], acc[i][2], acc[i][3]);
        }
    }
}

// ------------------------------------------------- V transpose + bf16 split
__global__ __launch_bounds__(256) void prep_v_kernel() {
    __shared__ float Vs[128][68];
    int bh = blockIdx.y, kt = blockIdx.x, tid = threadIdx.x;
    const float* src = g_v + ((size_t)bh * NN + kt * 128) * DD;
    for (int i = tid; i < 2048; i += 256) {
        int r = i >> 4, c = (i & 15) * 4;
        *(float4*)&Vs[r][c] = *(const float4*)(src + r * 64 + c);
    }
    __syncthreads();
    __nv_bfloat16* dh = g_vth + (size_t)(bh * 32 + kt) * 64 * 128;
    __nv_bfloat16* dl = g_vtl + (size_t)(bh * 32 + kt) * 64 * 128;
    for (int j = tid; j < 8192; j += 256) {
        int d = j >> 7, k = j & 127;
        split_store(dh, dl, (size_t)d * 128 + k, Vs[k][d]);
    }
}

// ---- K-tile cp for attention (tile [128][72] bf16, hi plane + lo plane)
__device__ __forceinline__ void attn_cpK(unsigned dK, const __nv_bfloat16* kh,
                                         const __nv_bfloat16* kl, int tid) {
    for (int i = tid; i < 1024; i += 256) {
        int r = i >> 3, j = i & 7;
        unsigned off = r * 144 + j * 16;
        size_t g = (size_t)r * 64 + j * 8;
        cp16(dK + off,         kh + g);
        cp16(dK + 18432 + off, kl + g);
    }
}

// ------------------------------------------------- attention pass 1 (pipelined)
// smem: QH 0, QL 18432, K double buffers at 36864 (36864 each) -> 110592 B
#define A1_K0 36864
#define A1_SMEM 110592
__global__ __launch_bounds__(256) void attn1_mma_kernel() {
    extern __shared__ char sm[];
    unsigned sb = smem_u32(sm);
    __nv_bfloat16* QH = (__nv_bfloat16*)sm;
    __nv_bfloat16* QL = (__nv_bfloat16*)(sm + 18432);
    int tid = threadIdx.x, wid = tid >> 5, lane = tid & 31;
    int bh = blockIdx.y, qt = blockIdx.x;
    const __nv_bfloat16* khg = g_kh + (size_t)bh * NN * DD;
    const __nv_bfloat16* klg = g_kl + (size_t)bh * NN * DD;
    {
        const __nv_bfloat16* qh = g_qh + ((size_t)bh * NN + qt * 128) * DD;
        const __nv_bfloat16* ql = g_ql + ((size_t)bh * NN + qt * 128) * DD;
        for (int i = tid; i < 1024; i += 256) {
            int r = i >> 3, j = i & 7;
            *(uint4*)(QH + r * 72 + j * 8) = *(const uint4*)(qh + r * 64 + j * 8);
            *(uint4*)(QL + r * 72 + j * 8) = *(const uint4*)(ql + r * 64 + j * 8);
        }
    }
    attn_cpK(sb + A1_K0, khg, klg, tid); CP_COMMIT();
    int arow = wid * 16 + (lane >> 2);
    float racc0 = 0.f, racc1 = 0.f;
    for (int kt = 0; kt < 32; kt++) {
        if (kt < 31) {
            attn_cpK(sb + A1_K0 + ((kt + 1) & 1) * 36864,
                     khg + (size_t)(kt + 1) * 128 * 64, klg + (size_t)(kt + 1) * 128 * 64, tid);
            CP_COMMIT(); CP_WAIT(1);
        } else CP_WAIT(0);
        __syncthreads();
        const __nv_bfloat16* KH = (const __nv_bfloat16*)(sm + A1_K0 + (kt & 1) * 36864);
        const __nv_bfloat16* KL = KH + 9216;
        float sacc[16][4] = {};
        #pragma unroll
        for (int kk = 0; kk < 4; kk++) {
            int acol = kk * 16 + (lane & 3) * 2;
            unsigned ah[4], al[4];
            ah[0] = *(unsigned*)(QH + arow * 72 + acol);
            ah[1] = *(unsigned*)(QH + (arow + 8) * 72 + acol);
            ah[2] = *(unsigned*)(QH + arow * 72 + acol + 8);
            ah[3] = *(unsigned*)(QH + (arow + 8) * 72 + acol + 8);
            al[0] = *(unsigned*)(QL + arow * 72 + acol);
            al[1] = *(unsigned*)(QL + (arow + 8) * 72 + acol);
            al[2] = *(unsigned*)(QL + arow * 72 + acol + 8);
            al[3] = *(unsigned*)(QL + (arow + 8) * 72 + acol + 8);
            #pragma unroll
            for (int nf = 0; nf < 16; nf++) {
                int brow = nf * 8 + (lane >> 2);
                unsigned b0 = *(unsigned*)(KH + brow * 72 + acol);
                unsigned b1 = *(unsigned*)(KH + brow * 72 + acol + 8);
                unsigned c0 = *(unsigned*)(KL + brow * 72 + acol);
                unsigned c1 = *(unsigned*)(KL + brow * 72 + acol + 8);
                mma16816(sacc[nf], ah, b0, b1);
                mma16816(sacc[nf], ah, c0, c1);
                mma16816(sacc[nf], al, b0, b1);
            }
        }
        #pragma unroll
        for (int nf = 0; nf < 16; nf++) {
            racc0 += exp2f(sacc[nf][0]) + exp2f(sacc[nf][1]);
            racc1 += exp2f(sacc[nf][2]) + exp2f(sacc[nf][3]);
        }
        __syncthreads();
    }
    racc0 += __shfl_xor_sync(0xffffffffu, racc0, 1);
    racc0 += __shfl_xor_sync(0xffffffffu, racc0, 2);
    racc1 += __shfl_xor_sync(0xffffffffu, racc1, 1);
    racc1 += __shfl_xor_sync(0xffffffffu, racc1, 2);
    if ((lane & 3) == 0) {
        size_t base = (size_t)bh * NN + qt * 128 + arow;
        g_rinv[base]     = 1.0f / racc0;
        g_rinv[base + 8] = 1.0f / racc1;
    }
}

// ------------------------------------------------- attention pass 2 (pipelined)
// smem: WS 0 (8x128 fp32 = 4096B), QH 4096, QL 22528, K bufs 40960 (2x36864),
//       VH 114688, VL 132096 -> 149504 B
#define A2_QH  4096
#define A2_QL  22528
#define A2_K0  40960
#define A2_VH  114688
#define A2_SMEM 149504
__global__ __launch_bounds__(256) void attn2_mma_kernel() {
    extern __shared__ char sm[];
    unsigned sb = smem_u32(sm);
    float (*WS)[128] = (float (*)[128])sm;      // per-warp importance partials
    __nv_bfloat16* QH = (__nv_bfloat16*)(sm + A2_QH);
    __nv_bfloat16* QL = (__nv_bfloat16*)(sm + A2_QL);
    __nv_bfloat16* VH = (__nv_bfloat16*)(sm + A2_VH);
    __nv_bfloat16* VL = (__nv_bfloat16*)(sm + A2_VH + 17408);
    int tid = threadIdx.x, wid = tid >> 5, lane = tid & 31;
    int bh = blockIdx.y, qt = blockIdx.x;
    int b = bh >> 3;
    const __nv_bfloat16* khg = g_kh + (size_t)bh * NN * DD;
    const __nv_bfloat16* klg = g_kl + (size_t)bh * NN * DD;
    const __nv_bfloat16* vhg = g_vth + (size_t)bh * NN * DD;
    const __nv_bfloat16* vlg = g_vtl + (size_t)bh * NN * DD;

    {
        const __nv_bfloat16* qh = g_qh + ((size_t)bh * NN + qt * 128) * DD;
        const __nv_bfloat16* ql = g_ql + ((size_t)bh * NN + qt * 128) * DD;
        for (int i = tid; i < 1024; i += 256) {
            int r = i >> 3, j = i & 7;
            *(uint4*)(QH + r * 72 + j * 8) = *(const uint4*)(qh + r * 64 + j * 8);
            *(uint4*)(QL + r * 72 + j * 8) = *(const uint4*)(ql + r * 64 + j * 8);
        }
    }
    attn_cpK(sb + A2_K0, khg, klg, tid); CP_COMMIT();
    int arow = wid * 16 + (lane >> 2);
    float rinv0 = g_rinv[(size_t)bh * NN + qt * 128 + arow];
    float rinv1 = g_rinv[(size_t)bh * NN + qt * 128 + arow + 8];
    float oacc[8][4] = {};

    for (int kt = 0; kt < 32; kt++) {
        {   // V(kt) into single buffer
            const __nv_bfloat16* vh = vhg + (size_t)kt * 64 * 128;
            const __nv_bfloat16* vl = vlg + (size_t)kt * 64 * 128;
            for (int i = tid; i < 1024; i += 256) {
                int r = i >> 4, j = i & 15;
                unsigned off = r * 272 + j * 16;
                size_t g = (size_t)r * 128 + j * 8;
                cp16(sb + A2_VH + off,         vh + g);
                cp16(sb + A2_VH + 17408 + off, vl + g);
            }
            CP_COMMIT();
        }
        if (kt < 31) {
            attn_cpK(sb + A2_K0 + ((kt + 1) & 1) * 36864,
                     khg + (size_t)(kt + 1) * 128 * 64, klg + (size_t)(kt + 1) * 128 * 64, tid);
            CP_COMMIT();
        }
        if (kt < 31) CP_WAIT(2); else CP_WAIT(1);   // K(kt) ready
        __syncthreads();
        const __nv_bfloat16* KH = (const __nv_bfloat16*)(sm + A2_K0 + (kt & 1) * 36864);
        const __nv_bfloat16* KL = KH + 9216;
        // ---- S = Q K^T
        float sacc[16][4] = {};
        #pragma unroll
        for (int kk = 0; kk < 4; kk++) {
            int acol = kk * 16 + (lane & 3) * 2;
            unsigned ah[4], al[4];
            ah[0] = *(unsigned*)(QH + arow * 72 + acol);
            ah[1] = *(unsigned*)(QH + (arow + 8) * 72 + acol);
            ah[2] = *(unsigned*)(QH + arow * 72 + acol + 8);
            ah[3] = *(unsigned*)(QH + (arow + 8) * 72 + acol + 8);
            al[0] = *(unsigned*)(QL + arow * 72 + acol);
            al[1] = *(unsigned*)(QL + (arow + 8) * 72 + acol);
            al[2] = *(unsigned*)(QL + arow * 72 + acol + 8);
            al[3] = *(unsigned*)(QL + (arow + 8) * 72 + acol + 8);
            #pragma unroll
            for (int nf = 0; nf < 16; nf++) {
                int brow = nf * 8 + (lane >> 2);
                unsigned b0 = *(unsigned*)(KH + brow * 72 + acol);
                unsigned b1 = *(unsigned*)(KH + brow * 72 + acol + 8);
                unsigned c0 = *(unsigned*)(KL + brow * 72 + acol);
                unsigned c1 = *(unsigned*)(KL + brow * 72 + acol + 8);
                mma16816(sacc[nf], ah, b0, b1);
                mma16816(sacc[nf], ah, c0, c1);
                mma16816(sacc[nf], al, b0, b1);
            }
        }
        // ---- p = exp2(s)*rinv; per-warp column partials (NO atomics —
        //      deterministic; fixed-order fp64 reduction below fixes the
        //      R9 replay-nondeterminism at the top-k boundary)
        #pragma unroll
        for (int nf = 0; nf < 16; nf++) {
            sacc[nf][0] = exp2f(sacc[nf][0]) * rinv0;
            sacc[nf][1] = exp2f(sacc[nf][1]) * rinv0;
            sacc[nf][2] = exp2f(sacc[nf][2]) * rinv1;
            sacc[nf][3] = exp2f(sacc[nf][3]) * rinv1;
            float s0 = sacc[nf][0] + sacc[nf][2];
            float s1 = sacc[nf][1] + sacc[nf][3];
            s0 += __shfl_xor_sync(0xffffffffu, s0, 4);
            s0 += __shfl_xor_sync(0xffffffffu, s0, 8);
            s0 += __shfl_xor_sync(0xffffffffu, s0, 16);
            s1 += __shfl_xor_sync(0xffffffffu, s1, 4);
            s1 += __shfl_xor_sync(0xffffffffu, s1, 8);
            s1 += __shfl_xor_sync(0xffffffffu, s1, 16);
            if (lane < 4) {
                WS[wid][nf * 8 + lane * 2]     = s0;
                WS[wid][nf * 8 + lane * 2 + 1] = s1;
            }
        }
        if (kt < 31) CP_WAIT(1); else CP_WAIT(0);   // V(kt) ready (also fences WS)
        __syncthreads();
        // ---- deterministic importance flush: fixed-order fp64 column sums
        if (tid < 128) {
            double ds = 0.0;
            #pragma unroll
            for (int w2 = 0; w2 < 8; w2++) ds += (double)WS[w2][tid];
            atomicAdd(&g_imp[(size_t)b * NN + kt * 128 + tid], ds);
        }
        // ---- O += P V
        #pragma unroll
        for (int t = 0; t < 8; t++) {
            unsigned ah[4], al[4];
            split2(sacc[2*t][0],   sacc[2*t][1],   ah[0], al[0]);
            split2(sacc[2*t][2],   sacc[2*t][3],   ah[1], al[1]);
            split2(sacc[2*t+1][0], sacc[2*t+1][1], ah[2], al[2]);
            split2(sacc[2*t+1][2], sacc[2*t+1][3], ah[3], al[3]);
            int bcol = t * 16 + (lane & 3) * 2;
            #pragma unroll
            for (int nf = 0; nf < 8; nf++) {
                int brow = nf * 8 + (lane >> 2);
                unsigned b0 = *(unsigned*)(VH + brow * 136 + bcol);
                unsigned b1 = *(unsigned*)(VH + brow * 136 + bcol + 8);
                unsigned c0 = *(unsigned*)(VL + brow * 136 + bcol);
                unsigned c1 = *(unsigned*)(VL + brow * 136 + bcol + 8);
                mma16816(oacc[nf], ah, b0, b1);
                mma16816(oacc[nf], ah, c0, c1);
                mma16816(oacc[nf], al, b0, b1);
            }
        }
        __syncthreads();
    }
    // ---- write O (fp32, [b,h,n,d])
    {
        size_t row0 = (size_t)bh * NN + qt * 128 + arow;
        float* o0 = g_o + row0 * DD;
        float* o1 = g_o + (row0 + 8) * DD;
        int col = (lane & 3) * 2;
        #pragma unroll
        for (int nf = 0; nf < 8; nf++) {
            *(float2*)(o0 + nf * 8 + col) = make_float2(oacc[nf][0], oacc[nf][1]);
            *(float2*)(o1 + nf * 8 + col) = make_float2(oacc[nf][2], oacc[nf][3]);
        }
    }
}

// ------------------------------------------------- projection GEMM (scalar, R6)
__global__ __launch_bounds__(256) void proj_gemm_kernel(
        const float* __restrict__ w, const float* __restrict__ bias) {
    __shared__ float As[64][36];
    __shared__ float Bs[32][64];
    int tid = threadIdx.x;
    int tx = tid & 15, ty = tid >> 4;
    int tx4 = tx * 4, ty4 = ty * 4;
    int m0 = blockIdx.y * 64;
    int j0 = blockIdx.x * 64;
    int bb = m0 >> 12, n0 = m0 & 4095;
    float acc[4][4] = {};
    for (int k0 = 0; k0 < 512; k0 += 32) {
        int h = k0 >> 6;
        int dd0 = k0 & 63;
        const float* Ap = g_o + (size_t)((bb * HH + h) * NN + n0) * DD + dd0;
        #pragma unroll
        for (int t = 0; t < 2; t++) {
            int l = tid + t * 256;
            int r = l >> 3, c = (l & 7) * 4;
            *(float4*)&As[r][c] = *(const float4*)(Ap + (size_t)r * 64 + c);
        }
        #pragma unroll
        for (int t = 0; t < 2; t++) {
            int l = tid + t * 256;
            int r = l >> 4, c = (l & 15) * 4;
            *(float4*)&Bs[r][c] = *(const float4*)(w + (size_t)(k0 + r) * 512 + j0 + c);
        }
        __syncthreads();
        #pragma unroll 4
        for (int kk = 0; kk < 32; kk += 4) {
            float a[4][4], b[4][4];
            #pragma unroll
            for (int i = 0; i < 4; i++) *(float4*)a[i] = *(const float4*)&As[ty4 + i][kk];
            #pragma unroll
            for (int q = 0; q < 4; q++) *(float4*)b[q] = *(const float4*)&Bs[kk + q][tx4];
            #pragma unroll
            for (int q = 0; q < 4; q++)
                #pragma unroll
                for (int i = 0; i < 4; i++)
                    #pragma unroll
                    for (int j = 0; j < 4; j++)
                        acc[i][j] += a[i][q] * b[q][j];
        }
        __syncthreads();
    }
    float4 bi = *(const float4*)(bias + j0 + tx4);
    #pragma unroll
    for (int i = 0; i < 4; i++) {
        int m = m0 + ty4 + i;
        float4 o4 = make_float4(acc[i][0] + bi.x, acc[i][1] + bi.y,
                                acc[i][2] + bi.z, acc[i][3] + bi.w);
        *(float4*)(g_out + (size_t)m * CC + j0 + tx4) = o4;
    }
}

// ------------------------------------------------- top-K (bitonic, fp64) + gather
__global__ __launch_bounds__(1024) void topk_gather_kernel(float* __restrict__ out) {
    __shared__ double sv[4096];
    __shared__ int    si[4096];
    int b = blockIdx.x, tid = threadIdx.x;
    for (int t = tid; t < 4096; t += 1024) { sv[t] = g_imp[b * NN + t]; si[t] = t; }
    __syncthreads();
    for (int k = 2; k <= 4096; k <<= 1) {
        for (int j = k >> 1; j > 0; j >>= 1) {
            for (int t = tid; t < 4096; t += 1024) {
                int p = t ^ j;
                if (p > t) {
                    double va = sv[t], vb = sv[p];
                    int ia = si[t], ib = si[p];
                    bool beforeAB = (va > vb) || (va == vb && ia < ib);
                    bool up = ((t & k) == 0);
                    if (up ? !beforeAB : beforeAB) {
                        sv[t] = vb; sv[p] = va; si[t] = ib; si[p] = ia;
                    }
                }
            }
            __syncthreads();
        }
    }
    for (int e = tid; e < KP * CC; e += 1024) {
        int kk = e >> 9, c = e & 511;
        out[(size_t)b * KP * CC + e] = g_out[(size_t)(b * NN + si[kk]) * CC + c];
    }
}

// ---------------------------------------------------------------- launcher
extern "C" void kernel_launch(void* const* d_in, const int* in_sizes, int n_in,
                              void* d_out, int out_size) {
    const float* x      = (const float*)d_in[0];
    const float* w_qkv  = (const float*)d_in[1];
    const float* w_proj = (const float*)d_in[2];
    const float* b_proj = (const float*)d_in[3];
    float* out = (float*)d_out;
    (void)in_sizes; (void)n_in; (void)out_size;

    cudaFuncSetAttribute(attn1_mma_kernel, cudaFuncAttributeMaxDynamicSharedMemorySize, A1_SMEM);
    cudaFuncSetAttribute(attn2_mma_kernel, cudaFuncAttributeMaxDynamicSharedMemorySize, A2_SMEM);

    zero_imp_kernel<<<8, 1024>>>();
    qkv_gemm_kernel<<<dim3(24, 128), 256>>>(x, w_qkv);
    prep_v_kernel<<<dim3(32, 16), 256>>>();
    attn1_mma_kernel<<<dim3(32, 16), 256, A1_SMEM>>>();
    attn2_mma_kernel<<<dim3(32, 16), 256, A2_SMEM>>>();
    proj_gemm_kernel<<<dim3(8, 128), 256>>>(w_proj, b_proj);
    topk_gather_kernel<<<2, 1024>>>(out);
}